// round 1
// baseline (speedup 1.0000x reference)
#include <cuda_runtime.h>
#include <cstdint>

#define NN 50000
#define NE 800000
#define KDIM 256
#define HDIM 64

// ---------------- scratch (device globals; no runtime allocation) ----------------
__device__ float g_fts[(size_t)4 * NN * HDIM];     // 4 x [N,64] GEMM outputs (51.2 MB)
__device__ int   g_cnt[2 * NN];                    // per-row edge counts (adj, diff)
__device__ int   g_ptr[2 * (NN + 1)];              // CSR row pointers
__device__ int   g_fill[2 * NN];                   // scatter cursors
__device__ int   g_csr_col[2 * NE];                // CSR column indices
__device__ float g_csr_w[2 * NE];                  // CSR edge weights

// ---------------- zero counts ----------------
__global__ void zero_cnt_kernel() {
    int i = blockIdx.x * blockDim.x + threadIdx.x;
    if (i < 2 * NN) g_cnt[i] = 0;
}

// ---------------- histogram rows ----------------
__global__ void hist_kernel(const int* __restrict__ adj_rows,
                            const int* __restrict__ diff_rows) {
    int set = blockIdx.y;
    const int* rows = set ? diff_rows : adj_rows;
    int i = blockIdx.x * blockDim.x + threadIdx.x;
    if (i < NE) atomicAdd(&g_cnt[set * NN + rows[i]], 1);
}

// ---------------- exclusive scan (one block per edge set) ----------------
__global__ void scan_kernel() {
    int set = blockIdx.x;
    __shared__ int sh[1024];
    int t = threadIdx.x;
    const int C = (NN + 1023) / 1024;   // 49
    int start = t * C;
    int stop = start + C; if (stop > NN) stop = NN;
    int sum = 0;
    for (int i = start; i < stop; ++i) sum += g_cnt[set * NN + i];
    sh[t] = sum;
    __syncthreads();
    // Hillis-Steele inclusive scan
    for (int off = 1; off < 1024; off <<= 1) {
        int v = (t >= off) ? sh[t - off] : 0;
        __syncthreads();
        sh[t] += v;
        __syncthreads();
    }
    int run = (t > 0) ? sh[t - 1] : 0;  // exclusive prefix of this chunk
    for (int i = start; i < stop; ++i) {
        g_ptr[set * (NN + 1) + i] = run;
        g_fill[set * NN + i] = run;
        run += g_cnt[set * NN + i];
    }
    if (t == 1023) g_ptr[set * (NN + 1) + NN] = sh[1023];
}

// ---------------- scatter edges into CSR order ----------------
__global__ void scatter_kernel(const int* __restrict__ adj_rows,
                               const int* __restrict__ adj_cols,
                               const float* __restrict__ adj_w,
                               const int* __restrict__ diff_rows,
                               const int* __restrict__ diff_cols,
                               const float* __restrict__ diff_w) {
    int set = blockIdx.y;
    const int* rows  = set ? diff_rows : adj_rows;
    const int* cols  = set ? diff_cols : adj_cols;
    const float* wts = set ? diff_w    : adj_w;
    int i = blockIdx.x * blockDim.x + threadIdx.x;
    if (i >= NE) return;
    int r = rows[i];
    int pos = atomicAdd(&g_fill[set * NN + r], 1);
    g_csr_col[set * NE + pos] = cols[i];
    g_csr_w[set * NE + pos]   = wts[i];
}

// ---------------- GEMM: fts[s] = X_s @ W_{s&1} ----------------
// 64x64 tile per block, 256 threads, 4x4 register micro-tile, K-chunks of 16.
__global__ void gemm_kernel(const float* __restrict__ X0, const float* __restrict__ X1,
                            const float* __restrict__ X2, const float* __restrict__ X3,
                            const float* __restrict__ W1, const float* __restrict__ W2) {
    int s = blockIdx.z;
    const float* X = (s == 0) ? X0 : (s == 1) ? X1 : (s == 2) ? X2 : X3;
    const float* W = (s & 1) ? W2 : W1;
    float* F = g_fts + (size_t)s * NN * HDIM;

    __shared__ float As[16][68];   // transposed A tile, padded (272B rows, 16B aligned)
    __shared__ float Bs[16][64];

    int tid = threadIdx.x;         // 0..255
    int tx = tid & 15;             // output col group (4 cols each)
    int ty = tid >> 4;             // output row group (4 rows each)
    int row0 = blockIdx.x * 64;

    float acc[4][4] = {};

    for (int k0 = 0; k0 < KDIM; k0 += 16) {
        // load A tile (64 rows x 16 k), store transposed
        {
            int r = tid >> 2;          // 0..63
            int c = (tid & 3) * 4;     // 0,4,8,12
            int gr = row0 + r; if (gr >= NN) gr = NN - 1;
            float4 v = *reinterpret_cast<const float4*>(&X[(size_t)gr * KDIM + k0 + c]);
            As[c + 0][r] = v.x; As[c + 1][r] = v.y;
            As[c + 2][r] = v.z; As[c + 3][r] = v.w;
        }
        // load B tile (16 k x 64 cols)
        {
            int kk = tid >> 4;         // 0..15
            int c  = (tid & 15) * 4;
            *reinterpret_cast<float4*>(&Bs[kk][c]) =
                *reinterpret_cast<const float4*>(&W[(size_t)(k0 + kk) * HDIM + c]);
        }
        __syncthreads();
#pragma unroll
        for (int kk = 0; kk < 16; ++kk) {
            float4 a = *reinterpret_cast<const float4*>(&As[kk][ty * 4]);
            float4 b = *reinterpret_cast<const float4*>(&Bs[kk][tx * 4]);
            float av[4] = {a.x, a.y, a.z, a.w};
            float bv[4] = {b.x, b.y, b.z, b.w};
#pragma unroll
            for (int i = 0; i < 4; ++i)
#pragma unroll
                for (int j = 0; j < 4; ++j)
                    acc[i][j] += av[i] * bv[j];
        }
        __syncthreads();
    }
#pragma unroll
    for (int i = 0; i < 4; ++i) {
        int gr = row0 + ty * 4 + i;
        if (gr < NN) {
            float4 v = {acc[i][0], acc[i][1], acc[i][2], acc[i][3]};
            *reinterpret_cast<float4*>(&F[(size_t)gr * HDIM + tx * 4]) = v;
        }
    }
}

// ---------------- aggregation: out[s][r][h] = PReLU(sum_e w*fts[s][col][h] + b) ----------------
// block: tx = h (64), ty = 4 rows. grid.z = slot.
__global__ void agg_kernel(const float* __restrict__ b1, const float* __restrict__ a1,
                           const float* __restrict__ b2, const float* __restrict__ a2,
                           float* __restrict__ out) {
    int s = blockIdx.z;
    int set = s & 1;                      // even slots: adj/W1/b1/a1; odd: diff/W2/b2/a2
    int row = blockIdx.x * 4 + threadIdx.y;
    int h = threadIdx.x;
    if (row >= NN) return;

    const float* fts = g_fts + (size_t)s * NN * HDIM;
    const int*   cols = g_csr_col + (size_t)set * NE;
    const float* wv   = g_csr_w   + (size_t)set * NE;
    int beg = g_ptr[set * (NN + 1) + row];
    int end = g_ptr[set * (NN + 1) + row + 1];

    float acc = set ? b2[h] : b1[h];
    for (int j = beg; j < end; ++j) {
        int c = cols[j];
        acc += wv[j] * fts[(size_t)c * HDIM + h];
    }
    float a = set ? a2[0] : a1[0];
    out[((size_t)s * NN + row) * HDIM + h] = (acc >= 0.0f) ? acc : a * acc;
}

// ---------------- launch ----------------
extern "C" void kernel_launch(void* const* d_in, const int* in_sizes, int n_in,
                              void* d_out, int out_size) {
    const float* bf        = (const float*)d_in[0];
    const float* bl        = (const float*)d_in[1];
    const float* shuf_fts  = (const float*)d_in[2];
    const float* shuf_fls  = (const float*)d_in[3];
    const int*   adj_rows  = (const int*)d_in[4];
    const int*   adj_cols  = (const int*)d_in[5];
    const float* adj_w     = (const float*)d_in[6];
    const int*   diff_rows = (const int*)d_in[7];
    const int*   diff_cols = (const int*)d_in[8];
    const float* diff_w    = (const float*)d_in[9];
    const float* W1        = (const float*)d_in[10];
    const float* b1        = (const float*)d_in[11];
    const float* a1        = (const float*)d_in[12];
    const float* W2        = (const float*)d_in[13];
    const float* b2        = (const float*)d_in[14];
    const float* a2        = (const float*)d_in[15];
    float* out = (float*)d_out;

    // 1. CSR build
    zero_cnt_kernel<<<(2 * NN + 255) / 256, 256>>>();
    {
        dim3 grid((NE + 255) / 256, 2);
        hist_kernel<<<grid, 256>>>(adj_rows, diff_rows);
    }
    scan_kernel<<<2, 1024>>>();
    {
        dim3 grid((NE + 255) / 256, 2);
        scatter_kernel<<<grid, 256>>>(adj_rows, adj_cols, adj_w,
                                      diff_rows, diff_cols, diff_w);
    }

    // 2. dense GEMMs (4 slots)
    {
        dim3 grid((NN + 63) / 64, 1, 4);
        gemm_kernel<<<grid, 256>>>(bf, bl, shuf_fts, shuf_fls, W1, W2);
    }

    // 3. atomic-free aggregation + bias + PReLU
    {
        dim3 grid((NN + 3) / 4, 1, 4);
        dim3 block(HDIM, 4);
        agg_kernel<<<grid, block>>>(b1, a1, b2, a2, out);
    }
}

// round 2
// speedup vs baseline: 1.3754x; 1.3754x over previous
#include <cuda_runtime.h>
#include <cstdint>

#define NN 50000
#define NE 800000
#define KDIM 256
#define HDIM 64

// ---------------- scratch (device globals; no runtime allocation) ----------------
__device__ float g_fts[(size_t)4 * NN * HDIM];     // 4 x [N,64] GEMM outputs (51.2 MB)
__device__ int   g_cnt[2 * NN];                    // per-row edge counts (adj, diff)
__device__ int   g_ptr[2 * (NN + 1)];              // CSR row pointers
__device__ int   g_fill[2 * NN];                   // scatter cursors
__device__ int   g_csr_col[2 * NE];                // CSR column indices
__device__ float g_csr_w[2 * NE];                  // CSR edge weights

// ---------------- zero counts ----------------
__global__ void zero_cnt_kernel() {
    int i = blockIdx.x * blockDim.x + threadIdx.x;
    if (i < 2 * NN) g_cnt[i] = 0;
}

// ---------------- histogram rows (4 edges/thread for MLP) ----------------
__global__ void hist_kernel(const int* __restrict__ adj_rows,
                            const int* __restrict__ diff_rows) {
    int set = blockIdx.y;
    const int* rows = set ? diff_rows : adj_rows;
    int i = (blockIdx.x * blockDim.x + threadIdx.x) * 4;
    if (i + 3 < NE) {
        int4 r = *reinterpret_cast<const int4*>(&rows[i]);
        atomicAdd(&g_cnt[set * NN + r.x], 1);
        atomicAdd(&g_cnt[set * NN + r.y], 1);
        atomicAdd(&g_cnt[set * NN + r.z], 1);
        atomicAdd(&g_cnt[set * NN + r.w], 1);
    } else {
        for (int j = i; j < NE; ++j) atomicAdd(&g_cnt[set * NN + rows[j]], 1);
    }
}

// ---------------- exclusive scan (one block per edge set) ----------------
__global__ void scan_kernel() {
    int set = blockIdx.x;
    __shared__ int sh[1024];
    int t = threadIdx.x;
    const int C = (NN + 1023) / 1024;   // 49
    int start = t * C;
    int stop = start + C; if (stop > NN) stop = NN;
    int sum = 0;
    for (int i = start; i < stop; ++i) sum += g_cnt[set * NN + i];
    sh[t] = sum;
    __syncthreads();
    for (int off = 1; off < 1024; off <<= 1) {
        int v = (t >= off) ? sh[t - off] : 0;
        __syncthreads();
        sh[t] += v;
        __syncthreads();
    }
    int run = (t > 0) ? sh[t - 1] : 0;
    for (int i = start; i < stop; ++i) {
        g_ptr[set * (NN + 1) + i] = run;
        g_fill[set * NN + i] = run;
        run += g_cnt[set * NN + i];
    }
    if (t == 1023) g_ptr[set * (NN + 1) + NN] = sh[1023];
}

// ---------------- scatter edges into CSR order (4 edges/thread) ----------------
__global__ void scatter_kernel(const int* __restrict__ adj_rows,
                               const int* __restrict__ adj_cols,
                               const float* __restrict__ adj_w,
                               const int* __restrict__ diff_rows,
                               const int* __restrict__ diff_cols,
                               const float* __restrict__ diff_w) {
    int set = blockIdx.y;
    const int* rows  = set ? diff_rows : adj_rows;
    const int* cols  = set ? diff_cols : adj_cols;
    const float* wts = set ? diff_w    : adj_w;
    int i = (blockIdx.x * blockDim.x + threadIdx.x) * 4;
    int* ccol = g_csr_col + (size_t)set * NE;
    float* cw = g_csr_w + (size_t)set * NE;
    int* fill = g_fill + set * NN;
    if (i + 3 < NE) {
        int4 r = *reinterpret_cast<const int4*>(&rows[i]);
        int4 c = *reinterpret_cast<const int4*>(&cols[i]);
        float4 w = *reinterpret_cast<const float4*>(&wts[i]);
        int p0 = atomicAdd(&fill[r.x], 1);
        int p1 = atomicAdd(&fill[r.y], 1);
        int p2 = atomicAdd(&fill[r.z], 1);
        int p3 = atomicAdd(&fill[r.w], 1);
        ccol[p0] = c.x; cw[p0] = w.x;
        ccol[p1] = c.y; cw[p1] = w.y;
        ccol[p2] = c.z; cw[p2] = w.z;
        ccol[p3] = c.w; cw[p3] = w.w;
    } else {
        for (int j = i; j < NE; ++j) {
            int p = atomicAdd(&fill[rows[j]], 1);
            ccol[p] = cols[j]; cw[p] = wts[j];
        }
    }
}

// ---------------- GEMM: fts[s] = X_s @ W_{s&1} ----------------
// 128x64 tile per block, 256 threads, 8x4 register micro-tile, K-chunks of 16,
// register prefetch of next K-tile (global latency hidden behind FFMA).
__global__ void __launch_bounds__(256) gemm_kernel(
        const float* __restrict__ X0, const float* __restrict__ X1,
        const float* __restrict__ X2, const float* __restrict__ X3,
        const float* __restrict__ W1, const float* __restrict__ W2) {
    int s = blockIdx.z;
    const float* X = (s == 0) ? X0 : (s == 1) ? X1 : (s == 2) ? X2 : X3;
    const float* W = (s & 1) ? W2 : W1;
    float* F = g_fts + (size_t)s * NN * HDIM;

    __shared__ float As[16][132];   // transposed A tile (k-major), 132*4B rows (16B aligned)
    __shared__ float Bs[16][64];

    int tid = threadIdx.x;         // 0..255
    int tx = tid & 15;             // output col group (4 cols)
    int ty = tid >> 4;             // output row group (8 rows)
    int row0 = blockIdx.x * 128;

    // A-load mapping: 2x float4 per thread (row lr, k offsets lc, lc+4)
    int lr = tid >> 1;             // 0..127
    int lc = (tid & 1) * 8;        // 0 or 8
    int gr = row0 + lr; if (gr >= NN) gr = NN - 1;
    const float* Xrow = X + (size_t)gr * KDIM;
    // B-load mapping: 1 float4 per thread
    int bk = tid >> 4;             // 0..15
    int bc = (tid & 15) * 4;

    float4 a0 = *reinterpret_cast<const float4*>(Xrow + lc);
    float4 a1 = *reinterpret_cast<const float4*>(Xrow + lc + 4);
    float4 bv0 = *reinterpret_cast<const float4*>(&W[(size_t)bk * HDIM + bc]);

    float acc[8][4] = {};

    for (int k0 = 0; k0 < KDIM; k0 += 16) {
        As[lc + 0][lr] = a0.x; As[lc + 1][lr] = a0.y;
        As[lc + 2][lr] = a0.z; As[lc + 3][lr] = a0.w;
        As[lc + 4][lr] = a1.x; As[lc + 5][lr] = a1.y;
        As[lc + 6][lr] = a1.z; As[lc + 7][lr] = a1.w;
        *reinterpret_cast<float4*>(&Bs[bk][bc]) = bv0;
        __syncthreads();

        if (k0 + 16 < KDIM) {   // prefetch next K-tile
            a0 = *reinterpret_cast<const float4*>(Xrow + k0 + 16 + lc);
            a1 = *reinterpret_cast<const float4*>(Xrow + k0 + 16 + lc + 4);
            bv0 = *reinterpret_cast<const float4*>(&W[(size_t)(k0 + 16 + bk) * HDIM + bc]);
        }

#pragma unroll
        for (int kk = 0; kk < 16; ++kk) {
            float4 av0 = *reinterpret_cast<const float4*>(&As[kk][ty * 8]);
            float4 av1 = *reinterpret_cast<const float4*>(&As[kk][ty * 8 + 4]);
            float4 bv = *reinterpret_cast<const float4*>(&Bs[kk][tx * 4]);
            float av[8] = {av0.x, av0.y, av0.z, av0.w, av1.x, av1.y, av1.z, av1.w};
            float bw[4] = {bv.x, bv.y, bv.z, bv.w};
#pragma unroll
            for (int i = 0; i < 8; ++i)
#pragma unroll
                for (int j = 0; j < 4; ++j)
                    acc[i][j] += av[i] * bw[j];
        }
        __syncthreads();
    }
#pragma unroll
    for (int i = 0; i < 8; ++i) {
        int orow = row0 + ty * 8 + i;
        if (orow < NN) {
            float4 v = {acc[i][0], acc[i][1], acc[i][2], acc[i][3]};
            *reinterpret_cast<float4*>(&F[(size_t)orow * HDIM + tx * 4]) = v;
        }
    }
}

// ---------------- aggregation: out[s][r][h] = PReLU(sum w*fts[s][col][h] + b) ----------------
// One warp per row per edge-set; lane covers 2 h (float2); both slots of the set
// (s and s+2 share the CSR) accumulated together; 2-edge unroll for MLP.
__global__ void __launch_bounds__(256) agg_kernel(
        const float* __restrict__ b1, const float* __restrict__ a1,
        const float* __restrict__ b2, const float* __restrict__ a2,
        float* __restrict__ out) {
    int set = blockIdx.z;                     // 0: adj (slots 0,2), 1: diff (slots 1,3)
    int row = blockIdx.x * 8 + threadIdx.y;
    if (row >= NN) return;
    int h = threadIdx.x * 2;                  // lane -> 2 h values

    const float* ftsA = g_fts + (size_t)set * NN * HDIM;        // slot = set
    const float* ftsB = g_fts + (size_t)(set + 2) * NN * HDIM;  // slot = set+2
    const int*   cols = g_csr_col + (size_t)set * NE;
    const float* wv   = g_csr_w   + (size_t)set * NE;
    int beg = g_ptr[set * (NN + 1) + row];
    int end = g_ptr[set * (NN + 1) + row + 1];

    float2 accA = {0.f, 0.f}, accB = {0.f, 0.f};
    int j = beg;
    for (; j + 1 < end; j += 2) {
        int c0 = cols[j], c1 = cols[j + 1];
        float w0 = wv[j], w1 = wv[j + 1];
        float2 f0a = *reinterpret_cast<const float2*>(&ftsA[(size_t)c0 * HDIM + h]);
        float2 f0b = *reinterpret_cast<const float2*>(&ftsB[(size_t)c0 * HDIM + h]);
        float2 f1a = *reinterpret_cast<const float2*>(&ftsA[(size_t)c1 * HDIM + h]);
        float2 f1b = *reinterpret_cast<const float2*>(&ftsB[(size_t)c1 * HDIM + h]);
        accA.x += w0 * f0a.x; accA.y += w0 * f0a.y;
        accB.x += w0 * f0b.x; accB.y += w0 * f0b.y;
        accA.x += w1 * f1a.x; accA.y += w1 * f1a.y;
        accB.x += w1 * f1b.x; accB.y += w1 * f1b.y;
    }
    if (j < end) {
        int c0 = cols[j];
        float w0 = wv[j];
        float2 f0a = *reinterpret_cast<const float2*>(&ftsA[(size_t)c0 * HDIM + h]);
        float2 f0b = *reinterpret_cast<const float2*>(&ftsB[(size_t)c0 * HDIM + h]);
        accA.x += w0 * f0a.x; accA.y += w0 * f0a.y;
        accB.x += w0 * f0b.x; accB.y += w0 * f0b.y;
    }

    const float* bb = set ? b2 : b1;
    float slope = set ? a2[0] : a1[0];
    float2 bias = *reinterpret_cast<const float2*>(&bb[h]);

    float2 oA = {accA.x + bias.x, accA.y + bias.y};
    float2 oB = {accB.x + bias.x, accB.y + bias.y};
    oA.x = (oA.x >= 0.f) ? oA.x : slope * oA.x;
    oA.y = (oA.y >= 0.f) ? oA.y : slope * oA.y;
    oB.x = (oB.x >= 0.f) ? oB.x : slope * oB.x;
    oB.y = (oB.y >= 0.f) ? oB.y : slope * oB.y;

    *reinterpret_cast<float2*>(&out[((size_t)set * NN + row) * HDIM + h]) = oA;
    *reinterpret_cast<float2*>(&out[((size_t)(set + 2) * NN + row) * HDIM + h]) = oB;
}

// ---------------- launch ----------------
extern "C" void kernel_launch(void* const* d_in, const int* in_sizes, int n_in,
                              void* d_out, int out_size) {
    const float* bf        = (const float*)d_in[0];
    const float* bl        = (const float*)d_in[1];
    const float* shuf_fts  = (const float*)d_in[2];
    const float* shuf_fls  = (const float*)d_in[3];
    const int*   adj_rows  = (const int*)d_in[4];
    const int*   adj_cols  = (const int*)d_in[5];
    const float* adj_w     = (const float*)d_in[6];
    const int*   diff_rows = (const int*)d_in[7];
    const int*   diff_cols = (const int*)d_in[8];
    const float* diff_w    = (const float*)d_in[9];
    const float* W1        = (const float*)d_in[10];
    const float* b1        = (const float*)d_in[11];
    const float* a1        = (const float*)d_in[12];
    const float* W2        = (const float*)d_in[13];
    const float* b2        = (const float*)d_in[14];
    const float* a2        = (const float*)d_in[15];
    float* out = (float*)d_out;

    static cudaStream_t s1 = nullptr;
    static cudaEvent_t e_fork = nullptr, e_join = nullptr;
    if (!s1) {
        cudaStreamCreateWithFlags(&s1, cudaStreamNonBlocking);
        cudaEventCreateWithFlags(&e_fork, cudaEventDisableTiming);
        cudaEventCreateWithFlags(&e_join, cudaEventDisableTiming);
    }

    // fork: CSR build on s1, GEMM on the capture (default) stream
    cudaEventRecord(e_fork, 0);
    cudaStreamWaitEvent(s1, e_fork, 0);

    zero_cnt_kernel<<<(2 * NN + 255) / 256, 256, 0, s1>>>();
    {
        dim3 grid((NE / 4 + 255) / 256, 2);
        hist_kernel<<<grid, 256, 0, s1>>>(adj_rows, diff_rows);
    }
    scan_kernel<<<2, 1024, 0, s1>>>();
    {
        dim3 grid((NE / 4 + 255) / 256, 2);
        scatter_kernel<<<grid, 256, 0, s1>>>(adj_rows, adj_cols, adj_w,
                                             diff_rows, diff_cols, diff_w);
    }
    cudaEventRecord(e_join, s1);

    // dense GEMMs (4 slots) on default stream, concurrent with CSR build
    {
        dim3 grid((NN + 127) / 128, 1, 4);
        gemm_kernel<<<grid, 256>>>(bf, bl, shuf_fts, shuf_fls, W1, W2);
    }

    // join, then aggregation + bias + PReLU
    cudaStreamWaitEvent(0, e_join, 0);
    {
        dim3 grid((NN + 7) / 8, 1, 2);
        dim3 block(32, 8);
        agg_kernel<<<grid, block>>>(b1, a1, b2, a2, out);
    }
}

// round 5
// speedup vs baseline: 1.6491x; 1.1990x over previous
#include <cuda_runtime.h>
#include <cstdint>

#define NN 50000
#define NE 800000
#define KDIM 256
#define HDIM 64
#define MTILE 128
#define CH 32                   // K floats per SMEM stage
#define NCHUNK (KDIM / CH)      // 8
#define ASTR 36                 // A smem stride (floats): bank (4r+k)%32 conflict-free
#define BSTR 72                 // B smem stride (floats): >=64, bank (8k+n)%32 conflict-free

// ---------------- scratch (device globals; no runtime allocation) ----------------
__device__ float g_fts[(size_t)4 * NN * HDIM];   // 4 x [N,64] GEMM outputs
__device__ int   g_cnt[2 * NN];
__device__ int   g_ptr[2 * (NN + 1)];
__device__ int   g_fill[2 * NN];
__device__ int2  g_csr[(size_t)2 * NE];          // packed {col, w bits}

// ---------------- helpers ----------------
__device__ __forceinline__ uint32_t f2tf32(float f) {
    uint32_t u;
    asm("cvt.rna.tf32.f32 %0, %1;" : "=r"(u) : "f"(f));
    return u;
}
__device__ __forceinline__ void mma_tf32(float& c0, float& c1, float& c2, float& c3,
                                         uint32_t a0, uint32_t a1, uint32_t a2, uint32_t a3,
                                         uint32_t b0, uint32_t b1) {
    asm volatile("mma.sync.aligned.m16n8k8.row.col.f32.tf32.tf32.f32 "
                 "{%0,%1,%2,%3}, {%4,%5,%6,%7}, {%8,%9}, {%0,%1,%2,%3};"
                 : "+f"(c0), "+f"(c1), "+f"(c2), "+f"(c3)
                 : "r"(a0), "r"(a1), "r"(a2), "r"(a3), "r"(b0), "r"(b1));
}

// ---------------- CSR build ----------------
__global__ void zero_cnt_kernel() {
    int i = blockIdx.x * blockDim.x + threadIdx.x;
    if (i < 2 * NN) g_cnt[i] = 0;
}

__global__ void hist_kernel(const int* __restrict__ adj_rows,
                            const int* __restrict__ diff_rows) {
    int set = blockIdx.y;
    const int* rows = set ? diff_rows : adj_rows;
    int i = (blockIdx.x * blockDim.x + threadIdx.x) * 4;
    if (i + 3 < NE) {
        int4 r = *reinterpret_cast<const int4*>(&rows[i]);
        atomicAdd(&g_cnt[set * NN + r.x], 1);
        atomicAdd(&g_cnt[set * NN + r.y], 1);
        atomicAdd(&g_cnt[set * NN + r.z], 1);
        atomicAdd(&g_cnt[set * NN + r.w], 1);
    } else {
        for (int j = i; j < NE; ++j) atomicAdd(&g_cnt[set * NN + rows[j]], 1);
    }
}

__global__ void scan_kernel() {
    int set = blockIdx.x;
    __shared__ int sh[1024];
    int t = threadIdx.x;
    const int C = (NN + 1023) / 1024;
    int start = t * C;
    int stop = start + C; if (stop > NN) stop = NN;
    int sum = 0;
    for (int i = start; i < stop; ++i) sum += g_cnt[set * NN + i];
    sh[t] = sum;
    __syncthreads();
    for (int off = 1; off < 1024; off <<= 1) {
        int v = (t >= off) ? sh[t - off] : 0;
        __syncthreads();
        sh[t] += v;
        __syncthreads();
    }
    int run = (t > 0) ? sh[t - 1] : 0;
    for (int i = start; i < stop; ++i) {
        g_ptr[set * (NN + 1) + i] = run;
        g_fill[set * NN + i] = run;
        run += g_cnt[set * NN + i];
    }
    if (t == 1023) g_ptr[set * (NN + 1) + NN] = sh[1023];
}

__global__ void scatter_kernel(const int* __restrict__ adj_rows,
                               const int* __restrict__ adj_cols,
                               const float* __restrict__ adj_w,
                               const int* __restrict__ diff_rows,
                               const int* __restrict__ diff_cols,
                               const float* __restrict__ diff_w) {
    int set = blockIdx.y;
    const int* rows  = set ? diff_rows : adj_rows;
    const int* cols  = set ? diff_cols : adj_cols;
    const float* wts = set ? diff_w    : adj_w;
    int i = (blockIdx.x * blockDim.x + threadIdx.x) * 4;
    int2* csr = g_csr + (size_t)set * NE;
    int* fill = g_fill + set * NN;
    if (i + 3 < NE) {
        int4 r = *reinterpret_cast<const int4*>(&rows[i]);
        int4 c = *reinterpret_cast<const int4*>(&cols[i]);
        float4 w = *reinterpret_cast<const float4*>(&wts[i]);
        int p0 = atomicAdd(&fill[r.x], 1);
        int p1 = atomicAdd(&fill[r.y], 1);
        int p2 = atomicAdd(&fill[r.z], 1);
        int p3 = atomicAdd(&fill[r.w], 1);
        csr[p0] = make_int2(c.x, __float_as_int(w.x));
        csr[p1] = make_int2(c.y, __float_as_int(w.y));
        csr[p2] = make_int2(c.z, __float_as_int(w.z));
        csr[p3] = make_int2(c.w, __float_as_int(w.w));
    } else {
        for (int j = i; j < NE; ++j) {
            int p = atomicAdd(&fill[rows[j]], 1);
            csr[p] = make_int2(cols[j], __float_as_int(wts[j]));
        }
    }
}

// ---------------- TF32 mma.sync GEMM: fts[s] = X_s @ W_{s&1} ----------------
// CTA: 128x64 tile, 256 threads (8 warps). Warp: 32 rows x 32 cols
// (2 m-tiles x 4 n-tiles of m16n8k8). K staged in 32-float SMEM chunks.
__global__ void __launch_bounds__(256) gemm_mma_kernel(
        const float* __restrict__ X0, const float* __restrict__ X1,
        const float* __restrict__ X2, const float* __restrict__ X3,
        const float* __restrict__ W1, const float* __restrict__ W2) {
    int s = blockIdx.y;
    const float* X = (s == 0) ? X0 : (s == 1) ? X1 : (s == 2) ? X2 : X3;
    const float* W = (s & 1) ? W2 : W1;      // [256][64] row-major == B[k][n]
    float* F = g_fts + (size_t)s * NN * HDIM;

    __shared__ uint32_t As[MTILE * ASTR];    // 18.4 KB, tf32 bits
    __shared__ uint32_t Bs[CH * BSTR];       //  9.2 KB, tf32 bits

    int tid = threadIdx.x;
    int wid = tid >> 5;
    int lane = tid & 31;
    int gID = lane >> 2;      // 0..7
    int tg  = lane & 3;       // 0..3

    int wr = (wid & 3) * 32;  // warp row offset in tile
    int wc = (wid >> 2) * 32; // warp col offset in tile
    int row0 = blockIdx.x * MTILE;

    // A global load mapping: 2 threads/row, 16 consecutive floats each
    int ar = tid >> 1;                  // 0..127
    int ak = (tid & 1) * 16;            // 0 or 16
    int gr = row0 + ar; if (gr >= NN) gr = NN - 1;
    const float* Xrow = X + (size_t)gr * KDIM;
    // B global load mapping: 8 threads/k-row, 8 consecutive floats each
    int bk = tid >> 3;                  // 0..31
    int bn = (tid & 7) * 8;             // 0..56

    float c[2][4][4];
#pragma unroll
    for (int mt = 0; mt < 2; ++mt)
#pragma unroll
        for (int nt = 0; nt < 4; ++nt)
#pragma unroll
            for (int q = 0; q < 4; ++q) c[mt][nt][q] = 0.f;

    for (int ch = 0; ch < NCHUNK; ++ch) {
        int k0 = ch * CH;
        // stage A (128 x 32) as tf32
#pragma unroll
        for (int j = 0; j < 4; ++j) {
            float4 v = *reinterpret_cast<const float4*>(Xrow + k0 + ak + j * 4);
            uint32_t* d = &As[ar * ASTR + ak + j * 4];
            d[0] = f2tf32(v.x); d[1] = f2tf32(v.y);
            d[2] = f2tf32(v.z); d[3] = f2tf32(v.w);
        }
        // stage B (32 x 64) as tf32
#pragma unroll
        for (int j = 0; j < 2; ++j) {
            float4 v = *reinterpret_cast<const float4*>(&W[(size_t)(k0 + bk) * HDIM + bn + j * 4]);
            uint32_t* d = &Bs[bk * BSTR + bn + j * 4];
            d[0] = f2tf32(v.x); d[1] = f2tf32(v.y);
            d[2] = f2tf32(v.z); d[3] = f2tf32(v.w);
        }
        __syncthreads();

#pragma unroll
        for (int ks = 0; ks < 4; ++ks) {   // 4 x k8 steps
            int kk = ks * 8;
            uint32_t a[2][4];
#pragma unroll
            for (int mt = 0; mt < 2; ++mt) {
                int rb = wr + mt * 16;
                a[mt][0] = As[(rb + gID) * ASTR + kk + tg];
                a[mt][1] = As[(rb + gID + 8) * ASTR + kk + tg];
                a[mt][2] = As[(rb + gID) * ASTR + kk + tg + 4];
                a[mt][3] = As[(rb + gID + 8) * ASTR + kk + tg + 4];
            }
            uint32_t b[4][2];
#pragma unroll
            for (int nt = 0; nt < 4; ++nt) {
                int col = wc + nt * 8 + gID;
                b[nt][0] = Bs[(kk + tg) * BSTR + col];
                b[nt][1] = Bs[(kk + tg + 4) * BSTR + col];
            }
#pragma unroll
            for (int mt = 0; mt < 2; ++mt)
#pragma unroll
                for (int nt = 0; nt < 4; ++nt)
                    mma_tf32(c[mt][nt][0], c[mt][nt][1], c[mt][nt][2], c[mt][nt][3],
                             a[mt][0], a[mt][1], a[mt][2], a[mt][3],
                             b[nt][0], b[nt][1]);
        }
        __syncthreads();
    }

    // epilogue: c-frag (q0,q1)->(row, 2tg..+1), (q2,q3)->(row+8, ...)
#pragma unroll
    for (int mt = 0; mt < 2; ++mt) {
        int r0 = row0 + wr + mt * 16 + gID;
#pragma unroll
        for (int nt = 0; nt < 4; ++nt) {
            int col = wc + nt * 8 + 2 * tg;
            if (r0 < NN) {
                float2 v = {c[mt][nt][0], c[mt][nt][1]};
                *reinterpret_cast<float2*>(&F[(size_t)r0 * HDIM + col]) = v;
            }
            if (r0 + 8 < NN) {
                float2 v = {c[mt][nt][2], c[mt][nt][3]};
                *reinterpret_cast<float2*>(&F[(size_t)(r0 + 8) * HDIM + col]) = v;
            }
        }
    }
}

// ---------------- aggregation + bias + PReLU ----------------
__global__ void __launch_bounds__(256) agg_kernel(
        const float* __restrict__ b1, const float* __restrict__ a1,
        const float* __restrict__ b2, const float* __restrict__ a2,
        float* __restrict__ out) {
    int set = blockIdx.z;
    int row = blockIdx.x * 8 + threadIdx.y;
    if (row >= NN) return;
    int h = threadIdx.x * 2;

    const float* ftsA = g_fts + (size_t)set * NN * HDIM;
    const float* ftsB = g_fts + (size_t)(set + 2) * NN * HDIM;
    const int2*  csr  = g_csr + (size_t)set * NE;
    int beg = g_ptr[set * (NN + 1) + row];
    int end = g_ptr[set * (NN + 1) + row + 1];

    float2 accA = {0.f, 0.f}, accB = {0.f, 0.f};
    int j = beg;
    for (; j + 1 < end; j += 2) {
        int2 e0 = csr[j], e1 = csr[j + 1];
        float w0 = __int_as_float(e0.y), w1 = __int_as_float(e1.y);
        float2 f0a = *reinterpret_cast<const float2*>(&ftsA[(size_t)e0.x * HDIM + h]);
        float2 f0b = *reinterpret_cast<const float2*>(&ftsB[(size_t)e0.x * HDIM + h]);
        float2 f1a = *reinterpret_cast<const float2*>(&ftsA[(size_t)e1.x * HDIM + h]);
        float2 f1b = *reinterpret_cast<const float2*>(&ftsB[(size_t)e1.x * HDIM + h]);
        accA.x += w0 * f0a.x; accA.y += w0 * f0a.y;
        accB.x += w0 * f0b.x; accB.y += w0 * f0b.y;
        accA.x += w1 * f1a.x; accA.y += w1 * f1a.y;
        accB.x += w1 * f1b.x; accB.y += w1 * f1b.y;
    }
    if (j < end) {
        int2 e0 = csr[j];
        float w0 = __int_as_float(e0.y);
        float2 f0a = *reinterpret_cast<const float2*>(&ftsA[(size_t)e0.x * HDIM + h]);
        float2 f0b = *reinterpret_cast<const float2*>(&ftsB[(size_t)e0.x * HDIM + h]);
        accA.x += w0 * f0a.x; accA.y += w0 * f0a.y;
        accB.x += w0 * f0b.x; accB.y += w0 * f0b.y;
    }

    const float* bb = set ? b2 : b1;
    float slope = set ? a2[0] : a1[0];
    float2 bias = *reinterpret_cast<const float2*>(&bb[h]);

    float2 oA = {accA.x + bias.x, accA.y + bias.y};
    float2 oB = {accB.x + bias.x, accB.y + bias.y};
    oA.x = (oA.x >= 0.f) ? oA.x : slope * oA.x;
    oA.y = (oA.y >= 0.f) ? oA.y : slope * oA.y;
    oB.x = (oB.x >= 0.f) ? oB.x : slope * oB.x;
    oB.y = (oB.y >= 0.f) ? oB.y : slope * oB.y;

    *reinterpret_cast<float2*>(&out[((size_t)set * NN + row) * HDIM + h]) = oA;
    *reinterpret_cast<float2*>(&out[((size_t)(set + 2) * NN + row) * HDIM + h]) = oB;
}

// ---------------- launch ----------------
extern "C" void kernel_launch(void* const* d_in, const int* in_sizes, int n_in,
                              void* d_out, int out_size) {
    const float* bf        = (const float*)d_in[0];
    const float* bl        = (const float*)d_in[1];
    const float* shuf_fts  = (const float*)d_in[2];
    const float* shuf_fls  = (const float*)d_in[3];
    const int*   adj_rows  = (const int*)d_in[4];
    const int*   adj_cols  = (const int*)d_in[5];
    const float* adj_w     = (const float*)d_in[6];
    const int*   diff_rows = (const int*)d_in[7];
    const int*   diff_cols = (const int*)d_in[8];
    const float* diff_w    = (const float*)d_in[9];
    const float* W1        = (const float*)d_in[10];
    const float* b1        = (const float*)d_in[11];
    const float* a1        = (const float*)d_in[12];
    const float* W2        = (const float*)d_in[13];
    const float* b2        = (const float*)d_in[14];
    const float* a2        = (const float*)d_in[15];
    float* out = (float*)d_out;

    static cudaStream_t s1 = nullptr;
    static cudaEvent_t e_fork = nullptr, e_join = nullptr;
    if (!s1) {
        cudaStreamCreateWithFlags(&s1, cudaStreamNonBlocking);
        cudaEventCreateWithFlags(&e_fork, cudaEventDisableTiming);
        cudaEventCreateWithFlags(&e_join, cudaEventDisableTiming);
    }

    // fork: CSR build on s1, GEMM on the capture (default) stream
    cudaEventRecord(e_fork, 0);
    cudaStreamWaitEvent(s1, e_fork, 0);

    zero_cnt_kernel<<<(2 * NN + 255) / 256, 256, 0, s1>>>();
    {
        dim3 grid((NE / 4 + 255) / 256, 2);
        hist_kernel<<<grid, 256, 0, s1>>>(adj_rows, diff_rows);
    }
    scan_kernel<<<2, 1024, 0, s1>>>();
    {
        dim3 grid((NE / 4 + 255) / 256, 2);
        scatter_kernel<<<grid, 256, 0, s1>>>(adj_rows, adj_cols, adj_w,
                                             diff_rows, diff_cols, diff_w);
    }
    cudaEventRecord(e_join, s1);

    // TF32 mma GEMMs (4 slots) on default stream, concurrent with CSR build
    {
        dim3 grid((NN + MTILE - 1) / MTILE, 4);
        gemm_mma_kernel<<<grid, 256>>>(bf, bl, shuf_fts, shuf_fls, W1, W2);
    }

    // join, then aggregation + bias + PReLU
    cudaStreamWaitEvent(0, e_join, 0);
    {
        dim3 grid((NN + 7) / 8, 1, 2);
        dim3 block(32, 8);
        agg_kernel<<<grid, block>>>(b1, a1, b2, a2, out);
    }
}